// round 6
// baseline (speedup 1.0000x reference)
#include <cuda_runtime.h>
#include <cuda_bf16.h>
#include <math.h>
#include <stdint.h>

#define D_MODEL 1024
#define NHEAD   16
#define HDIM    64
#define FFH     2048
#define BATCH   4
#define SEQ     2048
#define NTOK    (BATCH * SEQ)   // 8192

// ---------------- scratch (alloc-free: __device__ globals) ----------------
__device__ __nv_bfloat16 g_hh[NTOK * D_MODEL];
__device__ __nv_bfloat16 g_hl[NTOK * D_MODEL];
__device__ __nv_bfloat16 g_qh[NTOK * 3 * D_MODEL];
__device__ __nv_bfloat16 g_ql[NTOK * 3 * D_MODEL];
__device__ __nv_bfloat16 g_ch[NTOK * D_MODEL];
__device__ __nv_bfloat16 g_cl[NTOK * D_MODEL];
__device__ float         g_x1[NTOK * D_MODEL];
__device__ __nv_bfloat16 g_fh[NTOK * FFH];
__device__ __nv_bfloat16 g_fl[NTOK * FFH];
// pre-split transposed weights  Wt[n][k] = W[k][n]
__device__ __nv_bfloat16 g_wqh[3 * D_MODEL * D_MODEL];
__device__ __nv_bfloat16 g_wql[3 * D_MODEL * D_MODEL];
__device__ __nv_bfloat16 g_woh[D_MODEL * D_MODEL];
__device__ __nv_bfloat16 g_wol[D_MODEL * D_MODEL];
__device__ __nv_bfloat16 g_w1h[FFH * D_MODEL];
__device__ __nv_bfloat16 g_w1l[FFH * D_MODEL];
__device__ __nv_bfloat16 g_w2h[D_MODEL * FFH];
__device__ __nv_bfloat16 g_w2l[D_MODEL * FFH];

// ======================= helpers =======================
__device__ __forceinline__ uint32_t smem_u32(const void* p) {
    uint32_t a;
    asm("{ .reg .u64 t; cvta.to.shared.u64 t, %1; cvt.u32.u64 %0, t; }" : "=r"(a) : "l"(p));
    return a;
}
__device__ __forceinline__ void cp16(uint32_t d, const void* s) {
    asm volatile("cp.async.cg.shared.global [%0], [%1], 16;" :: "r"(d), "l"(s));
}
__device__ __forceinline__ void cp_commit() {
    asm volatile("cp.async.commit_group;");
}
template <int N>
__device__ __forceinline__ void cp_wait() {
    asm volatile("cp.async.wait_group %0;" :: "n"(N));
}
__device__ __forceinline__ void ldmx4(uint32_t& r0, uint32_t& r1, uint32_t& r2, uint32_t& r3,
                                      uint32_t addr) {
    asm volatile("ldmatrix.sync.aligned.m8n8.x4.shared.b16 {%0,%1,%2,%3}, [%4];"
                 : "=r"(r0), "=r"(r1), "=r"(r2), "=r"(r3) : "r"(addr));
}
__device__ __forceinline__ void mma_bf16(float* d, const uint32_t* a, const uint32_t* b) {
    asm volatile(
        "mma.sync.aligned.m16n8k16.row.col.f32.bf16.bf16.f32 "
        "{%0,%1,%2,%3},{%4,%5,%6,%7},{%8,%9},{%0,%1,%2,%3};"
        : "+f"(d[0]), "+f"(d[1]), "+f"(d[2]), "+f"(d[3])
        : "r"(a[0]), "r"(a[1]), "r"(a[2]), "r"(a[3]), "r"(b[0]), "r"(b[1]));
}
__device__ __forceinline__ void split2(float a, float b, uint32_t& hi, uint32_t& lo) {
    __nv_bfloat16 ah = __float2bfloat16_rn(a), bh = __float2bfloat16_rn(b);
    float ar = a - __bfloat162float(ah);
    float br = b - __bfloat162float(bh);
    __nv_bfloat162 h = __halves2bfloat162(ah, bh);
    __nv_bfloat162 l = __halves2bfloat162(__float2bfloat16_rn(ar), __float2bfloat16_rn(br));
    hi = *reinterpret_cast<uint32_t*>(&h);
    lo = *reinterpret_cast<uint32_t*>(&l);
}
__device__ __forceinline__ float gelu_exact(float v) {
    return 0.5f * v * (1.0f + erff(v * 0.70710678118654752f));
}

// ======================= weight transpose + split =======================
__global__ __launch_bounds__(256) void wconv(const float* __restrict__ W,
                                             __nv_bfloat16* __restrict__ Wh,
                                             __nv_bfloat16* __restrict__ Wl,
                                             int N, int K) {
    __shared__ float t[32][33];
    int n0 = blockIdx.x * 32, k0 = blockIdx.y * 32;
    int tx = threadIdx.x & 31, ty = threadIdx.x >> 5;
    #pragma unroll
    for (int i = ty; i < 32; i += 8)
        t[i][tx] = W[(size_t)(k0 + i) * N + n0 + tx];
    __syncthreads();
    #pragma unroll
    for (int i = ty; i < 32; i += 8) {
        float v = t[tx][i];
        __nv_bfloat16 h = __float2bfloat16_rn(v);
        __nv_bfloat16 l = __float2bfloat16_rn(v - __bfloat162float(h));
        size_t o = (size_t)(n0 + i) * K + k0 + tx;
        Wh[o] = h; Wl[o] = l;
    }
}

// ======================= HMMA bf16-split GEMM (2 CTAs/SM) ==========
// C = A @ Wt^T + bias (+gelu)(+res); A hi/lo [M][K], Wt hi/lo [N][K] bf16.
// CTA 128x128, BK=32, 256 thr (warp grid 2m x 4n, warp tile 64x32),
// cp.async double-buffered, 2 CTAs/SM.
#define TPITCH 80
#define TILE_B (128 * TPITCH)          // 10240
#define BUF_B  (4 * TILE_B)            // 40960
#define GEMM_SMEM (2 * BUF_B)          // 81920

template <bool GELU, bool RES, bool OSPLIT>
__global__ __launch_bounds__(256, 2) void hmma_gemm(const __nv_bfloat16* __restrict__ Ah,
                                                    const __nv_bfloat16* __restrict__ Al,
                                                    const __nv_bfloat16* __restrict__ Bth,
                                                    const __nv_bfloat16* __restrict__ Btl,
                                                    const float* __restrict__ bias,
                                                    const float* __restrict__ R,
                                                    float* __restrict__ C,
                                                    __nv_bfloat16* __restrict__ Oh,
                                                    __nv_bfloat16* __restrict__ Ol,
                                                    int M, int N, int K) {
    extern __shared__ char smem[];
    const uint32_t sb = smem_u32(smem);
    const int tid = threadIdx.x;
    const int lane = tid & 31;
    const int wid = tid >> 5;
    const int wm = wid & 1;          // m half (64 rows)
    const int wn = wid >> 1;         // n slice (32 cols)
    const int m0 = blockIdx.y * 128, n0 = blockIdx.x * 128;

    const int srow = tid >> 1;                          // 0..127
    const uint32_t sby = (uint32_t)((tid & 1) * 32);    // byte offset 0 / 32
    const int skel = (tid & 1) * 16;                    // k element offset 0 / 16
    const uint32_t sdst = (uint32_t)(srow * TPITCH) + sby;

    float acc[4][4][4];
    #pragma unroll
    for (int i = 0; i < 4; i++)
        #pragma unroll
        for (int j = 0; j < 4; j++)
            #pragma unroll
            for (int l = 0; l < 4; l++) acc[i][j][l] = 0.f;

    const int nch = K >> 5;

    auto stage = [&](int c, int buf) {
        const int k0 = (c << 5) + skel;
        uint32_t d = sb + buf * BUF_B + sdst;
        const size_t ao = (size_t)(m0 + srow) * K + k0;
        const size_t bo = (size_t)(n0 + srow) * K + k0;
        cp16(d,                   Ah  + ao);
        cp16(d + 16,              Ah  + ao + 8);
        cp16(d + TILE_B,          Al  + ao);
        cp16(d + TILE_B + 16,     Al  + ao + 8);
        cp16(d + 2 * TILE_B,      Bth + bo);
        cp16(d + 2 * TILE_B + 16, Bth + bo + 8);
        cp16(d + 3 * TILE_B,      Btl + bo);
        cp16(d + 3 * TILE_B + 16, Btl + bo + 8);
        cp_commit();
    };

    stage(0, 0);
    if (nch > 1) stage(1, 1);

    for (int c = 0; c < nch; c++) {
        if (c + 1 < nch) cp_wait<1>(); else cp_wait<0>();
        __syncthreads();

        const uint32_t bufb = sb + (c & 1) * BUF_B;
        #pragma unroll
        for (int ks = 0; ks < 2; ks++) {
            const uint32_t kb = ks * 32;
            const uint32_t lrow = (lane & 15);
            const uint32_t lseg = (lane >> 4) << 4;
            uint32_t aH[4][4], aL[4][4], b4H[2][4], b4L[2][4];
            #pragma unroll
            for (int mt = 0; mt < 4; mt++) {
                uint32_t ar = (uint32_t)((wm * 64 + mt * 16 + lrow) * TPITCH) + kb + lseg;
                ldmx4(aH[mt][0], aH[mt][1], aH[mt][2], aH[mt][3], bufb + ar);
                ldmx4(aL[mt][0], aL[mt][1], aL[mt][2], aL[mt][3], bufb + TILE_B + ar);
            }
            #pragma unroll
            for (int np = 0; np < 2; np++) {
                uint32_t br = (uint32_t)((wn * 32 + np * 16 + lrow) * TPITCH) + kb + lseg;
                ldmx4(b4H[np][0], b4H[np][1], b4H[np][2], b4H[np][3], bufb + 2 * TILE_B + br);
                ldmx4(b4L[np][0], b4L[np][1], b4L[np][2], b4L[np][3], bufb + 3 * TILE_B + br);
            }
            #pragma unroll
            for (int nt = 0; nt < 4; nt++) {
                const int np = nt >> 1, sel = nt & 1;
                uint32_t bH[2] = {b4H[np][sel], b4H[np][sel + 2]};
                uint32_t bL[2] = {b4L[np][sel], b4L[np][sel + 2]};
                #pragma unroll
                for (int mt = 0; mt < 4; mt++) {
                    mma_bf16(acc[mt][nt], aH[mt], bH);
                    mma_bf16(acc[mt][nt], aL[mt], bH);
                    mma_bf16(acc[mt][nt], aH[mt], bL);
                }
            }
        }
        __syncthreads();
        if (c + 2 < nch) stage(c + 2, c & 1);
    }

    // ---- epilogue ----
    #pragma unroll
    for (int mt = 0; mt < 4; mt++) {
        #pragma unroll
        for (int nt = 0; nt < 4; nt++) {
            int col = n0 + wn * 32 + nt * 8 + (lane & 3) * 2;
            float b0 = bias[col], b1 = bias[col + 1];
            #pragma unroll
            for (int half = 0; half < 2; half++) {
                int row = m0 + wm * 64 + mt * 16 + (lane >> 2) + half * 8;
                float o0 = acc[mt][nt][half * 2 + 0] + b0;
                float o1 = acc[mt][nt][half * 2 + 1] + b1;
                if (GELU) { o0 = gelu_exact(o0); o1 = gelu_exact(o1); }
                if (RES) {
                    const float* rp = R + (size_t)row * N + col;
                    o0 += rp[0]; o1 += rp[1];
                }
                if (OSPLIT) {
                    uint32_t hi, lo;
                    split2(o0, o1, hi, lo);
                    *(uint32_t*)(Oh + (size_t)row * N + col) = hi;
                    *(uint32_t*)(Ol + (size_t)row * N + col) = lo;
                } else {
                    *(float2*)(C + (size_t)row * N + col) = make_float2(o0, o1);
                }
            }
        }
    }
}

// ======================= HMMA flash attention (pre-split qkv) ==============
#define AP 144
#define AQH 0
#define AQL 18432
#define AKH 36864
#define AKL 46080
#define AVH 55296
#define AVL 64512
#define ATT_SMEM 73728

__global__ __launch_bounds__(256, 2) void attn_hmma(const __nv_bfloat16* __restrict__ qh,
                                                    const __nv_bfloat16* __restrict__ ql,
                                                    __nv_bfloat16* __restrict__ ch,
                                                    __nv_bfloat16* __restrict__ cl) {
    extern __shared__ char sm[];
    const uint32_t sb = smem_u32(sm);
    const int tid = threadIdx.x;
    const int lane = tid & 31;
    const int wid = tid >> 5;
    const int b = blockIdx.z, h = blockIdx.y;
    const int q0 = blockIdx.x * 128;

    {
        const size_t qbase = ((size_t)(b * SEQ + q0)) * (3 * D_MODEL) + h * HDIM;
        #pragma unroll
        for (int rep = 0; rep < 4; rep++) {
            int idx = rep * 256 + tid;
            int row = idx >> 3;
            int seg = idx & 7;
            size_t src = qbase + (size_t)row * (3 * D_MODEL) + seg * 8;
            uint32_t dst = row * AP + seg * 16;
            *(uint4*)(sm + AQH + dst) = *(const uint4*)(qh + src);
            *(uint4*)(sm + AQL + dst) = *(const uint4*)(ql + src);
        }
    }

    float acc[8][4];
    #pragma unroll
    for (int i = 0; i < 8; i++)
        #pragma unroll
        for (int j = 0; j < 4; j++) acc[i][j] = 0.f;
    float mrow0 = -1e30f, mrow1 = -1e30f;
    float lrow0 = 0.f, lrow1 = 0.f;

    for (int kt = 0; kt < SEQ; kt += 64) {
        __syncthreads();
        {
            const size_t kbase = ((size_t)(b * SEQ + kt)) * (3 * D_MODEL) + D_MODEL + h * HDIM;
            #pragma unroll
            for (int rep = 0; rep < 2; rep++) {
                int idx = rep * 256 + tid;
                int row = idx >> 3;
                int seg = idx & 7;
                size_t src = kbase + (size_t)row * (3 * D_MODEL) + seg * 8;
                uint32_t dst = row * AP + seg * 16;
                *(uint4*)(sm + AKH + dst) = *(const uint4*)(qh + src);
                *(uint4*)(sm + AKL + dst) = *(const uint4*)(ql + src);
            }
            const size_t vbase = kbase + D_MODEL;
            #pragma unroll
            for (int rep = 0; rep < 4; rep++) {
                int idx = rep * 256 + tid;
                int key = idx >> 4;
                int d4 = (idx & 15) * 4;
                uint2 hv = *(const uint2*)(qh + vbase + (size_t)key * (3 * D_MODEL) + d4);
                uint2 lv = *(const uint2*)(ql + vbase + (size_t)key * (3 * D_MODEL) + d4);
                const __nv_bfloat16* hp = (const __nv_bfloat16*)&hv;
                const __nv_bfloat16* lp = (const __nv_bfloat16*)&lv;
                #pragma unroll
                for (int i = 0; i < 4; i++) {
                    *(__nv_bfloat16*)(sm + AVH + (d4 + i) * AP + key * 2) = hp[i];
                    *(__nv_bfloat16*)(sm + AVL + (d4 + i) * AP + key * 2) = lp[i];
                }
            }
        }
        __syncthreads();

        float sf[8][4];
        #pragma unroll
        for (int i = 0; i < 8; i++)
            #pragma unroll
            for (int j = 0; j < 4; j++) sf[i][j] = 0.f;

        #pragma unroll
        for (int ks = 0; ks < 4; ks++) {
            uint32_t qaddr = sb + AQH + (uint32_t)((wid * 16 + (lane & 15)) * AP)
                           + ks * 32 + ((lane >> 4) << 4);
            uint32_t qhf[4], qlf[4];
            ldmx4(qhf[0], qhf[1], qhf[2], qhf[3], qaddr);
            ldmx4(qlf[0], qlf[1], qlf[2], qlf[3], qaddr + (AQL - AQH));
            #pragma unroll
            for (int np = 0; np < 4; np++) {
                uint32_t kaddr = sb + AKH + (uint32_t)((np * 16 + (lane & 15)) * AP)
                               + ks * 32 + ((lane >> 4) << 4);
                uint32_t kh[4], kl[4];
                ldmx4(kh[0], kh[1], kh[2], kh[3], kaddr);
                ldmx4(kl[0], kl[1], kl[2], kl[3], kaddr + (AKL - AKH));
                uint32_t bh0[2] = {kh[0], kh[2]}, bh1[2] = {kh[1], kh[3]};
                uint32_t bl0[2] = {kl[0], kl[2]}, bl1[2] = {kl[1], kl[3]};
                mma_bf16(sf[2 * np + 0], qhf, bh0);
                mma_bf16(sf[2 * np + 0], qlf, bh0);
                mma_bf16(sf[2 * np + 0], qhf, bl0);
                mma_bf16(sf[2 * np + 1], qhf, bh1);
                mma_bf16(sf[2 * np + 1], qlf, bh1);
                mma_bf16(sf[2 * np + 1], qhf, bl1);
            }
        }
        #pragma unroll
        for (int nt = 0; nt < 8; nt++)
            #pragma unroll
            for (int j = 0; j < 4; j++) sf[nt][j] *= 0.125f;

        float tm0 = -1e30f, tm1 = -1e30f;
        #pragma unroll
        for (int nt = 0; nt < 8; nt++) {
            tm0 = fmaxf(tm0, fmaxf(sf[nt][0], sf[nt][1]));
            tm1 = fmaxf(tm1, fmaxf(sf[nt][2], sf[nt][3]));
        }
        #pragma unroll
        for (int o = 1; o < 4; o <<= 1) {
            tm0 = fmaxf(tm0, __shfl_xor_sync(0xffffffffu, tm0, o));
            tm1 = fmaxf(tm1, __shfl_xor_sync(0xffffffffu, tm1, o));
        }
        float mn0 = fmaxf(mrow0, tm0), mn1 = fmaxf(mrow1, tm1);
        float f0 = __expf(mrow0 - mn0), f1 = __expf(mrow1 - mn1);
        mrow0 = mn0; mrow1 = mn1;
        lrow0 *= f0; lrow1 *= f1;
        #pragma unroll
        for (int dt = 0; dt < 8; dt++) {
            acc[dt][0] *= f0; acc[dt][1] *= f0;
            acc[dt][2] *= f1; acc[dt][3] *= f1;
        }
        #pragma unroll
        for (int nt = 0; nt < 8; nt++) {
            sf[nt][0] = __expf(sf[nt][0] - mn0);
            sf[nt][1] = __expf(sf[nt][1] - mn0);
            sf[nt][2] = __expf(sf[nt][2] - mn1);
            sf[nt][3] = __expf(sf[nt][3] - mn1);
            lrow0 += sf[nt][0] + sf[nt][1];
            lrow1 += sf[nt][2] + sf[nt][3];
        }

        #pragma unroll
        for (int ks = 0; ks < 4; ks++) {
            int nt0 = 2 * ks, nt1 = 2 * ks + 1;
            uint32_t ph[4], pl[4];
            split2(sf[nt0][0], sf[nt0][1], ph[0], pl[0]);
            split2(sf[nt0][2], sf[nt0][3], ph[1], pl[1]);
            split2(sf[nt1][0], sf[nt1][1], ph[2], pl[2]);
            split2(sf[nt1][2], sf[nt1][3], ph[3], pl[3]);
            #pragma unroll
            for (int dp = 0; dp < 4; dp++) {
                uint32_t vaddr = sb + AVH + (uint32_t)((dp * 16 + (lane & 15)) * AP)
                               + ks * 32 + ((lane >> 4) << 4);
                uint32_t vh[4], vl[4];
                ldmx4(vh[0], vh[1], vh[2], vh[3], vaddr);
                ldmx4(vl[0], vl[1], vl[2], vl[3], vaddr + (AVL - AVH));
                uint32_t bh0[2] = {vh[0], vh[2]}, bh1[2] = {vh[1], vh[3]};
                uint32_t bl0[2] = {vl[0], vl[2]}, bl1[2] = {vl[1], vl[3]};
                mma_bf16(acc[2 * dp + 0], ph, bh0);
                mma_bf16(acc[2 * dp + 0], pl, bh0);
                mma_bf16(acc[2 * dp + 0], ph, bl0);
                mma_bf16(acc[2 * dp + 1], ph, bh1);
                mma_bf16(acc[2 * dp + 1], pl, bh1);
                mma_bf16(acc[2 * dp + 1], ph, bl1);
            }
        }
    }

    #pragma unroll
    for (int o = 1; o < 4; o <<= 1) {
        lrow0 += __shfl_xor_sync(0xffffffffu, lrow0, o);
        lrow1 += __shfl_xor_sync(0xffffffffu, lrow1, o);
    }
    float inv0 = 1.0f / lrow0, inv1 = 1.0f / lrow1;
    size_t t0 = (size_t)(b * SEQ + q0 + wid * 16 + (lane >> 2));
    size_t t1 = t0 + 8;
    int col = h * HDIM + (lane & 3) * 2;
    #pragma unroll
    for (int dt = 0; dt < 8; dt++) {
        uint32_t hi, lo;
        split2(acc[dt][0] * inv0, acc[dt][1] * inv0, hi, lo);
        *(uint32_t*)(ch + t0 * D_MODEL + col + dt * 8) = hi;
        *(uint32_t*)(cl + t0 * D_MODEL + col + dt * 8) = lo;
        split2(acc[dt][2] * inv1, acc[dt][3] * inv1, hi, lo);
        *(uint32_t*)(ch + t1 * D_MODEL + col + dt * 8) = hi;
        *(uint32_t*)(cl + t1 * D_MODEL + col + dt * 8) = lo;
    }
}

// ---------------- LayerNorm -> bf16 hi/lo ----------------
__global__ __launch_bounds__(256) void ln_kernel(const float* __restrict__ x,
                                                 const float* __restrict__ g,
                                                 const float* __restrict__ b,
                                                 __nv_bfloat16* __restrict__ oh,
                                                 __nv_bfloat16* __restrict__ ol) {
    int row = blockIdx.x;
    int tid = threadIdx.x;
    const float* xr = x + (size_t)row * D_MODEL;

    float4 xv = *(const float4*)(xr + tid * 4);
    float s  = xv.x + xv.y + xv.z + xv.w;
    float ss = xv.x * xv.x + xv.y * xv.y + xv.z * xv.z + xv.w * xv.w;

    __shared__ float red0[32], red1[32];
    #pragma unroll
    for (int o = 16; o > 0; o >>= 1) {
        s  += __shfl_xor_sync(0xffffffffu, s,  o);
        ss += __shfl_xor_sync(0xffffffffu, ss, o);
    }
    int warp = tid >> 5, lane = tid & 31;
    if (lane == 0) { red0[warp] = s; red1[warp] = ss; }
    __syncthreads();
    if (warp == 0) {
        float a  = (lane < 8) ? red0[lane] : 0.f;
        float a2 = (lane < 8) ? red1[lane] : 0.f;
        #pragma unroll
        for (int o = 4; o > 0; o >>= 1) {
            a  += __shfl_xor_sync(0xffffffffu, a,  o);
            a2 += __shfl_xor_sync(0xffffffffu, a2, o);
        }
        if (lane == 0) { red0[0] = a; red1[0] = a2; }
    }
    __syncthreads();

    float mean = red0[0] * (1.0f / D_MODEL);
    float var  = red1[0] * (1.0f / D_MODEL) - mean * mean;
    float rstd = rsqrtf(var + 1e-5f);

    float4 gv = *(const float4*)(g + tid * 4);
    float4 bv = *(const float4*)(b + tid * 4);
    float o0 = (xv.x - mean) * rstd * gv.x + bv.x;
    float o1 = (xv.y - mean) * rstd * gv.y + bv.y;
    float o2 = (xv.z - mean) * rstd * gv.z + bv.z;
    float o3 = (xv.w - mean) * rstd * gv.w + bv.w;
    uint32_t h01, l01, h23, l23;
    split2(o0, o1, h01, l01);
    split2(o2, o3, h23, l23);
    *(uint2*)(oh + (size_t)row * D_MODEL + tid * 4) = make_uint2(h01, h23);
    *(uint2*)(ol + (size_t)row * D_MODEL + tid * 4) = make_uint2(l01, l23);
}

// ---------------- launch ----------------
extern "C" void kernel_launch(void* const* d_in, const int* in_sizes, int n_in,
                              void* d_out, int out_size) {
    const float* x     = (const float*)d_in[0];
    const float* qkv_w = (const float*)d_in[1];
    const float* qkv_b = (const float*)d_in[2];
    const float* out_w = (const float*)d_in[3];
    const float* out_b = (const float*)d_in[4];
    const float* ff1_w = (const float*)d_in[5];
    const float* ff1_b = (const float*)d_in[6];
    const float* ff2_w = (const float*)d_in[7];
    const float* ff2_b = (const float*)d_in[8];
    const float* ln1_g = (const float*)d_in[9];
    const float* ln1_b = (const float*)d_in[10];
    const float* ln2_g = (const float*)d_in[11];
    const float* ln2_b = (const float*)d_in[12];
    float* out = (float*)d_out;

    __nv_bfloat16 *hh, *hl, *qh, *ql, *ch, *cl, *fh, *fl;
    __nv_bfloat16 *wqh, *wql, *woh, *wol, *w1h, *w1l, *w2h, *w2l;
    float* x1;
    cudaGetSymbolAddress((void**)&hh, g_hh);  cudaGetSymbolAddress((void**)&hl, g_hl);
    cudaGetSymbolAddress((void**)&qh, g_qh);  cudaGetSymbolAddress((void**)&ql, g_ql);
    cudaGetSymbolAddress((void**)&ch, g_ch);  cudaGetSymbolAddress((void**)&cl, g_cl);
    cudaGetSymbolAddress((void**)&fh, g_fh);  cudaGetSymbolAddress((void**)&fl, g_fl);
    cudaGetSymbolAddress((void**)&x1, g_x1);
    cudaGetSymbolAddress((void**)&wqh, g_wqh); cudaGetSymbolAddress((void**)&wql, g_wql);
    cudaGetSymbolAddress((void**)&woh, g_woh); cudaGetSymbolAddress((void**)&wol, g_wol);
    cudaGetSymbolAddress((void**)&w1h, g_w1h); cudaGetSymbolAddress((void**)&w1l, g_w1l);
    cudaGetSymbolAddress((void**)&w2h, g_w2h); cudaGetSymbolAddress((void**)&w2l, g_w2l);

    cudaFuncSetAttribute(hmma_gemm<false, false, true>,
                         cudaFuncAttributeMaxDynamicSharedMemorySize, GEMM_SMEM);
    cudaFuncSetAttribute(hmma_gemm<false, true, false>,
                         cudaFuncAttributeMaxDynamicSharedMemorySize, GEMM_SMEM);
    cudaFuncSetAttribute(hmma_gemm<true, false, true>,
                         cudaFuncAttributeMaxDynamicSharedMemorySize, GEMM_SMEM);
    cudaFuncSetAttribute(attn_hmma,
                         cudaFuncAttributeMaxDynamicSharedMemorySize, ATT_SMEM);

    // 0. weight conversion (transpose + bf16 split)
    wconv<<<dim3(3 * D_MODEL / 32, D_MODEL / 32), 256>>>(qkv_w, wqh, wql, 3 * D_MODEL, D_MODEL);
    wconv<<<dim3(D_MODEL / 32, D_MODEL / 32), 256>>>(out_w, woh, wol, D_MODEL, D_MODEL);
    wconv<<<dim3(FFH / 32, D_MODEL / 32), 256>>>(ff1_w, w1h, w1l, FFH, D_MODEL);
    wconv<<<dim3(D_MODEL / 32, FFH / 32), 256>>>(ff2_w, w2h, w2l, D_MODEL, FFH);

    // 1. h = LN1(x) -> hi/lo
    ln_kernel<<<NTOK, 256>>>(x, ln1_g, ln1_b, hh, hl);
    // 2. qkv = h @ qkv_w + qkv_b -> hi/lo
    hmma_gemm<false, false, true><<<dim3(3 * D_MODEL / 128, NTOK / 128), 256, GEMM_SMEM>>>(
        hh, hl, wqh, wql, qkv_b, nullptr, nullptr, qh, ql, NTOK, 3 * D_MODEL, D_MODEL);
    // 3. ctx = attention(qkv) -> hi/lo
    attn_hmma<<<dim3(SEQ / 128, NHEAD, BATCH), 256, ATT_SMEM>>>(qh, ql, ch, cl);
    // 4. x1 = ctx @ out_w + out_b + x   (fp32)
    hmma_gemm<false, true, false><<<dim3(D_MODEL / 128, NTOK / 128), 256, GEMM_SMEM>>>(
        ch, cl, woh, wol, out_b, x, x1, nullptr, nullptr, NTOK, D_MODEL, D_MODEL);
    // 5. h2 = LN2(x1) -> hi/lo
    ln_kernel<<<NTOK, 256>>>(x1, ln2_g, ln2_b, hh, hl);
    // 6. ffh = gelu(h2 @ ff1_w + ff1_b) -> hi/lo
    hmma_gemm<true, false, true><<<dim3(FFH / 128, NTOK / 128), 256, GEMM_SMEM>>>(
        hh, hl, w1h, w1l, ff1_b, nullptr, nullptr, fh, fl, NTOK, FFH, D_MODEL);
    // 7. out = ffh @ ff2_w + ff2_b + x1  (fp32)
    hmma_gemm<false, true, false><<<dim3(D_MODEL / 128, NTOK / 128), 256, GEMM_SMEM>>>(
        fh, fl, w2h, w2l, ff2_b, x1, out, nullptr, nullptr, NTOK, D_MODEL, FFH);
}

// round 7
// speedup vs baseline: 1.3567x; 1.3567x over previous
#include <cuda_runtime.h>
#include <cuda_fp16.h>
#include <math.h>
#include <stdint.h>

#define D_MODEL 1024
#define NHEAD   16
#define HDIM    64
#define FFH     2048
#define BATCH   4
#define SEQ     2048
#define NTOK    (BATCH * SEQ)   // 8192

// ---------------- scratch (alloc-free: __device__ globals) ----------------
__device__ __half g_hh[NTOK * D_MODEL];
__device__ __half g_hl[NTOK * D_MODEL];
__device__ __half g_qh[NTOK * 3 * D_MODEL];
__device__ __half g_ql[NTOK * 3 * D_MODEL];
__device__ __half g_ch[NTOK * D_MODEL];
__device__ __half g_cl[NTOK * D_MODEL];
__device__ float  g_x1[NTOK * D_MODEL];
__device__ __half g_fh[NTOK * FFH];
__device__ __half g_fl[NTOK * FFH];
// pre-converted transposed weights  Wt[n][k] = fp16(W[k][n])  (hi plane only)
__device__ __half g_wq[3 * D_MODEL * D_MODEL];
__device__ __half g_wo[D_MODEL * D_MODEL];
__device__ __half g_w1[FFH * D_MODEL];
__device__ __half g_w2[D_MODEL * FFH];

// ======================= helpers =======================
__device__ __forceinline__ uint32_t smem_u32(const void* p) {
    uint32_t a;
    asm("{ .reg .u64 t; cvta.to.shared.u64 t, %1; cvt.u32.u64 %0, t; }" : "=r"(a) : "l"(p));
    return a;
}
__device__ __forceinline__ void cp16(uint32_t d, const void* s) {
    asm volatile("cp.async.cg.shared.global [%0], [%1], 16;" :: "r"(d), "l"(s));
}
__device__ __forceinline__ void cp_commit() {
    asm volatile("cp.async.commit_group;");
}
template <int N>
__device__ __forceinline__ void cp_wait() {
    asm volatile("cp.async.wait_group %0;" :: "n"(N));
}
__device__ __forceinline__ void ldmx4(uint32_t& r0, uint32_t& r1, uint32_t& r2, uint32_t& r3,
                                      uint32_t addr) {
    asm volatile("ldmatrix.sync.aligned.m8n8.x4.shared.b16 {%0,%1,%2,%3}, [%4];"
                 : "=r"(r0), "=r"(r1), "=r"(r2), "=r"(r3) : "r"(addr));
}
__device__ __forceinline__ void mma_f16(float* d, const uint32_t* a, const uint32_t* b) {
    asm volatile(
        "mma.sync.aligned.m16n8k16.row.col.f32.f16.f16.f32 "
        "{%0,%1,%2,%3},{%4,%5,%6,%7},{%8,%9},{%0,%1,%2,%3};"
        : "+f"(d[0]), "+f"(d[1]), "+f"(d[2]), "+f"(d[3])
        : "r"(a[0]), "r"(a[1]), "r"(a[2]), "r"(a[3]), "r"(b[0]), "r"(b[1]));
}
// fp32 pair -> fp16 hi + fp16 residual(lo) packed
__device__ __forceinline__ void split2h(float a, float b, uint32_t& hi, uint32_t& lo) {
    __half ah = __float2half_rn(a), bh = __float2half_rn(b);
    float ar = a - __half2float(ah);
    float br = b - __half2float(bh);
    __half2 h = __halves2half2(ah, bh);
    __half2 l = __halves2half2(__float2half_rn(ar), __float2half_rn(br));
    hi = *reinterpret_cast<uint32_t*>(&h);
    lo = *reinterpret_cast<uint32_t*>(&l);
}
__device__ __forceinline__ float gelu_exact(float v) {
    return 0.5f * v * (1.0f + erff(v * 0.70710678118654752f));
}

// ======================= weight transpose + fp16 convert =======================
__global__ __launch_bounds__(256) void wconv(const float* __restrict__ W,
                                             __half* __restrict__ Wh,
                                             int N, int K) {
    __shared__ float t[32][33];
    int n0 = blockIdx.x * 32, k0 = blockIdx.y * 32;
    int tx = threadIdx.x & 31, ty = threadIdx.x >> 5;
    #pragma unroll
    for (int i = ty; i < 32; i += 8)
        t[i][tx] = W[(size_t)(k0 + i) * N + n0 + tx];
    __syncthreads();
    #pragma unroll
    for (int i = ty; i < 32; i += 8)
        Wh[(size_t)(n0 + i) * K + k0 + tx] = __float2half_rn(t[tx][i]);
}

// ======================= HMMA fp16 2-term GEMM =======================
// C = A @ Wt^T + bias (+gelu)(+res); A hi/lo fp16 [M][K], Wt fp16 [N][K].
// CTA 128x128, BK=32, 512 thr (warp 32x32), 3-stage cp.async pipeline.
#define TPITCH 80
#define TILE_B (128 * TPITCH)          // 10240
#define BUF_B  (3 * TILE_B)            // 30720 (AH, AL, BH)
#define NSTAGE 3
#define GEMM_SMEM (NSTAGE * BUF_B)     // 92160

template <bool GELU, bool RES, bool OSPLIT>
__global__ __launch_bounds__(512, 1) void hmma_gemm(const __half* __restrict__ Ah,
                                                    const __half* __restrict__ Al,
                                                    const __half* __restrict__ Bt,
                                                    const float* __restrict__ bias,
                                                    const float* __restrict__ R,
                                                    float* __restrict__ C,
                                                    __half* __restrict__ Oh,
                                                    __half* __restrict__ Ol,
                                                    int M, int N, int K) {
    extern __shared__ char smem[];
    const uint32_t sb = smem_u32(smem);
    const int tid = threadIdx.x;
    const int lane = tid & 31;
    const int wid = tid >> 5;
    const int wm = wid & 3;          // m slice (32 rows)
    const int wn = wid >> 2;         // n slice (32 cols)
    const int m0 = blockIdx.y * 128, n0 = blockIdx.x * 128;

    const int srow = tid >> 2;          // 0..127
    const int sseg = tid & 3;           // 16B segment (8 fp16)
    const uint32_t sdst = (uint32_t)(srow * TPITCH + sseg * 16);

    float acc[2][4][4];
    #pragma unroll
    for (int i = 0; i < 2; i++)
        #pragma unroll
        for (int j = 0; j < 4; j++)
            #pragma unroll
            for (int l = 0; l < 4; l++) acc[i][j][l] = 0.f;

    const int nch = K >> 5;

    auto stage = [&](int c, int buf) {
        const int k0 = (c << 5) + sseg * 8;
        uint32_t d = sb + buf * BUF_B + sdst;
        cp16(d,              Ah + (size_t)(m0 + srow) * K + k0);
        cp16(d + TILE_B,     Al + (size_t)(m0 + srow) * K + k0);
        cp16(d + 2 * TILE_B, Bt + (size_t)(n0 + srow) * K + k0);
        cp_commit();
    };

    stage(0, 0);
    if (nch > 1) stage(1, 1);
    if (nch > 2) stage(2, 2);

    int buf = 0;
    for (int c = 0; c < nch; c++) {
        cp_wait<2>();
        __syncthreads();

        const uint32_t bufb = sb + buf * BUF_B;
        const uint32_t lrow = (lane & 15);
        const uint32_t lseg = (lane >> 4) << 4;
        #pragma unroll
        for (int ks = 0; ks < 2; ks++) {
            const uint32_t kb = ks * 32;
            uint32_t aH[2][4], aL[2][4], b4[2][4];
            #pragma unroll
            for (int mt = 0; mt < 2; mt++) {
                uint32_t ar = (uint32_t)((wm * 32 + mt * 16 + lrow) * TPITCH) + kb + lseg;
                ldmx4(aH[mt][0], aH[mt][1], aH[mt][2], aH[mt][3], bufb + ar);
                ldmx4(aL[mt][0], aL[mt][1], aL[mt][2], aL[mt][3], bufb + TILE_B + ar);
            }
            #pragma unroll
            for (int np = 0; np < 2; np++) {
                uint32_t br = (uint32_t)((wn * 32 + np * 16 + lrow) * TPITCH) + kb + lseg;
                ldmx4(b4[np][0], b4[np][1], b4[np][2], b4[np][3], bufb + 2 * TILE_B + br);
            }
            #pragma unroll
            for (int nt = 0; nt < 4; nt++) {
                const int np = nt >> 1, sel = nt & 1;
                uint32_t bf[2] = {b4[np][sel], b4[np][sel + 2]};
                #pragma unroll
                for (int mt = 0; mt < 2; mt++) {
                    mma_f16(acc[mt][nt], aH[mt], bf);
                    mma_f16(acc[mt][nt], aL[mt], bf);
                }
            }
        }
        __syncthreads();
        if (c + NSTAGE < nch) stage(c + NSTAGE, buf);
        buf = (buf == NSTAGE - 1) ? 0 : buf + 1;
    }

    // ---- epilogue ----
    #pragma unroll
    for (int mt = 0; mt < 2; mt++) {
        #pragma unroll
        for (int nt = 0; nt < 4; nt++) {
            int col = n0 + wn * 32 + nt * 8 + (lane & 3) * 2;
            float b0 = bias[col], b1 = bias[col + 1];
            #pragma unroll
            for (int half = 0; half < 2; half++) {
                int row = m0 + wm * 32 + mt * 16 + (lane >> 2) + half * 8;
                float o0 = acc[mt][nt][half * 2 + 0] + b0;
                float o1 = acc[mt][nt][half * 2 + 1] + b1;
                if (GELU) { o0 = gelu_exact(o0); o1 = gelu_exact(o1); }
                if (RES) {
                    const float* rp = R + (size_t)row * N + col;
                    o0 += rp[0]; o1 += rp[1];
                }
                if (OSPLIT) {
                    uint32_t hi, lo;
                    split2h(o0, o1, hi, lo);
                    *(uint32_t*)(Oh + (size_t)row * N + col) = hi;
                    *(uint32_t*)(Ol + (size_t)row * N + col) = lo;
                } else {
                    *(float2*)(C + (size_t)row * N + col) = make_float2(o0, o1);
                }
            }
        }
    }
}

// ======================= HMMA fp16 flash attention =======================
// Q hi/lo, K hi, V hi.  S = QhKh + QlKh;  PV = PhVh + PlVh.
#define AP 144
#define AQH 0
#define AQL 18432
#define AKH 36864
#define AVH 46080
#define ATT_SMEM 55296

__global__ __launch_bounds__(256, 2) void attn_hmma(const __half* __restrict__ qh,
                                                    const __half* __restrict__ ql,
                                                    __half* __restrict__ ch,
                                                    __half* __restrict__ cl) {
    extern __shared__ char sm[];
    const uint32_t sb = smem_u32(sm);
    const int tid = threadIdx.x;
    const int lane = tid & 31;
    const int wid = tid >> 5;
    const int b = blockIdx.z, h = blockIdx.y;
    const int q0 = blockIdx.x * 128;

    // ---- stage Q [128][64] hi/lo ----
    {
        const size_t qbase = ((size_t)(b * SEQ + q0)) * (3 * D_MODEL) + h * HDIM;
        #pragma unroll
        for (int rep = 0; rep < 4; rep++) {
            int idx = rep * 256 + tid;
            int row = idx >> 3;
            int seg = idx & 7;
            size_t src = qbase + (size_t)row * (3 * D_MODEL) + seg * 8;
            uint32_t dst = row * AP + seg * 16;
            *(uint4*)(sm + AQH + dst) = *(const uint4*)(qh + src);
            *(uint4*)(sm + AQL + dst) = *(const uint4*)(ql + src);
        }
    }

    float acc[8][4];
    #pragma unroll
    for (int i = 0; i < 8; i++)
        #pragma unroll
        for (int j = 0; j < 4; j++) acc[i][j] = 0.f;
    float mrow0 = -1e30f, mrow1 = -1e30f;
    float lrow0 = 0.f, lrow1 = 0.f;

    for (int kt = 0; kt < SEQ; kt += 64) {
        __syncthreads();
        // ---- stage K [64][64] hi + V transposed [64 d][64 key] hi ----
        {
            const size_t kbase = ((size_t)(b * SEQ + kt)) * (3 * D_MODEL) + D_MODEL + h * HDIM;
            #pragma unroll
            for (int rep = 0; rep < 2; rep++) {
                int idx = rep * 256 + tid;
                int row = idx >> 3;
                int seg = idx & 7;
                size_t src = kbase + (size_t)row * (3 * D_MODEL) + seg * 8;
                *(uint4*)(sm + AKH + row * AP + seg * 16) = *(const uint4*)(qh + src);
            }
            const size_t vbase = kbase + D_MODEL;
            #pragma unroll
            for (int rep = 0; rep < 4; rep++) {
                int idx = rep * 256 + tid;
                int key = idx >> 4;
                int d4 = (idx & 15) * 4;
                uint2 hv = *(const uint2*)(qh + vbase + (size_t)key * (3 * D_MODEL) + d4);
                const __half* hp = (const __half*)&hv;
                #pragma unroll
                for (int i = 0; i < 4; i++)
                    *(__half*)(sm + AVH + (d4 + i) * AP + key * 2) = hp[i];
            }
        }
        __syncthreads();

        // ---- S = Q @ K^T ----
        float sf[8][4];
        #pragma unroll
        for (int i = 0; i < 8; i++)
            #pragma unroll
            for (int j = 0; j < 4; j++) sf[i][j] = 0.f;

        #pragma unroll
        for (int ks = 0; ks < 4; ks++) {
            uint32_t qaddr = sb + AQH + (uint32_t)((wid * 16 + (lane & 15)) * AP)
                           + ks * 32 + ((lane >> 4) << 4);
            uint32_t qhf[4], qlf[4];
            ldmx4(qhf[0], qhf[1], qhf[2], qhf[3], qaddr);
            ldmx4(qlf[0], qlf[1], qlf[2], qlf[3], qaddr + (AQL - AQH));
            #pragma unroll
            for (int np = 0; np < 4; np++) {
                uint32_t kaddr = sb + AKH + (uint32_t)((np * 16 + (lane & 15)) * AP)
                               + ks * 32 + ((lane >> 4) << 4);
                uint32_t kh[4];
                ldmx4(kh[0], kh[1], kh[2], kh[3], kaddr);
                uint32_t bh0[2] = {kh[0], kh[2]}, bh1[2] = {kh[1], kh[3]};
                mma_f16(sf[2 * np + 0], qhf, bh0);
                mma_f16(sf[2 * np + 0], qlf, bh0);
                mma_f16(sf[2 * np + 1], qhf, bh1);
                mma_f16(sf[2 * np + 1], qlf, bh1);
            }
        }
        #pragma unroll
        for (int nt = 0; nt < 8; nt++)
            #pragma unroll
            for (int j = 0; j < 4; j++) sf[nt][j] *= 0.125f;

        // ---- online softmax ----
        float tm0 = -1e30f, tm1 = -1e30f;
        #pragma unroll
        for (int nt = 0; nt < 8; nt++) {
            tm0 = fmaxf(tm0, fmaxf(sf[nt][0], sf[nt][1]));
            tm1 = fmaxf(tm1, fmaxf(sf[nt][2], sf[nt][3]));
        }
        #pragma unroll
        for (int o = 1; o < 4; o <<= 1) {
            tm0 = fmaxf(tm0, __shfl_xor_sync(0xffffffffu, tm0, o));
            tm1 = fmaxf(tm1, __shfl_xor_sync(0xffffffffu, tm1, o));
        }
        float mn0 = fmaxf(mrow0, tm0), mn1 = fmaxf(mrow1, tm1);
        float f0 = __expf(mrow0 - mn0), f1 = __expf(mrow1 - mn1);
        mrow0 = mn0; mrow1 = mn1;
        lrow0 *= f0; lrow1 *= f1;
        #pragma unroll
        for (int dt = 0; dt < 8; dt++) {
            acc[dt][0] *= f0; acc[dt][1] *= f0;
            acc[dt][2] *= f1; acc[dt][3] *= f1;
        }
        #pragma unroll
        for (int nt = 0; nt < 8; nt++) {
            sf[nt][0] = __expf(sf[nt][0] - mn0);
            sf[nt][1] = __expf(sf[nt][1] - mn0);
            sf[nt][2] = __expf(sf[nt][2] - mn1);
            sf[nt][3] = __expf(sf[nt][3] - mn1);
            lrow0 += sf[nt][0] + sf[nt][1];
            lrow1 += sf[nt][2] + sf[nt][3];
        }

        // ---- ctx += P @ V ----
        #pragma unroll
        for (int ks = 0; ks < 4; ks++) {
            int nt0 = 2 * ks, nt1 = 2 * ks + 1;
            uint32_t ph[4], pl[4];
            split2h(sf[nt0][0], sf[nt0][1], ph[0], pl[0]);
            split2h(sf[nt0][2], sf[nt0][3], ph[1], pl[1]);
            split2h(sf[nt1][0], sf[nt1][1], ph[2], pl[2]);
            split2h(sf[nt1][2], sf[nt1][3], ph[3], pl[3]);
            #pragma unroll
            for (int dp = 0; dp < 4; dp++) {
                uint32_t vaddr = sb + AVH + (uint32_t)((dp * 16 + (lane & 15)) * AP)
                               + ks * 32 + ((lane >> 4) << 4);
                uint32_t vh[4];
                ldmx4(vh[0], vh[1], vh[2], vh[3], vaddr);
                uint32_t bh0[2] = {vh[0], vh[2]}, bh1[2] = {vh[1], vh[3]};
                mma_f16(acc[2 * dp + 0], ph, bh0);
                mma_f16(acc[2 * dp + 0], pl, bh0);
                mma_f16(acc[2 * dp + 1], ph, bh1);
                mma_f16(acc[2 * dp + 1], pl, bh1);
            }
        }
    }

    // ---- epilogue: write ctx hi/lo ----
    #pragma unroll
    for (int o = 1; o < 4; o <<= 1) {
        lrow0 += __shfl_xor_sync(0xffffffffu, lrow0, o);
        lrow1 += __shfl_xor_sync(0xffffffffu, lrow1, o);
    }
    float inv0 = 1.0f / lrow0, inv1 = 1.0f / lrow1;
    size_t t0 = (size_t)(b * SEQ + q0 + wid * 16 + (lane >> 2));
    size_t t1 = t0 + 8;
    int col = h * HDIM + (lane & 3) * 2;
    #pragma unroll
    for (int dt = 0; dt < 8; dt++) {
        uint32_t hi, lo;
        split2h(acc[dt][0] * inv0, acc[dt][1] * inv0, hi, lo);
        *(uint32_t*)(ch + t0 * D_MODEL + col + dt * 8) = hi;
        *(uint32_t*)(cl + t0 * D_MODEL + col + dt * 8) = lo;
        split2h(acc[dt][2] * inv1, acc[dt][3] * inv1, hi, lo);
        *(uint32_t*)(ch + t1 * D_MODEL + col + dt * 8) = hi;
        *(uint32_t*)(cl + t1 * D_MODEL + col + dt * 8) = lo;
    }
}

// ---------------- LayerNorm -> fp16 hi/lo ----------------
__global__ __launch_bounds__(256) void ln_kernel(const float* __restrict__ x,
                                                 const float* __restrict__ g,
                                                 const float* __restrict__ b,
                                                 __half* __restrict__ oh,
                                                 __half* __restrict__ ol) {
    int row = blockIdx.x;
    int tid = threadIdx.x;
    const float* xr = x + (size_t)row * D_MODEL;

    float4 xv = *(const float4*)(xr + tid * 4);
    float s  = xv.x + xv.y + xv.z + xv.w;
    float ss = xv.x * xv.x + xv.y * xv.y + xv.z * xv.z + xv.w * xv.w;

    __shared__ float red0[32], red1[32];
    #pragma unroll
    for (int o = 16; o > 0; o >>= 1) {
        s  += __shfl_xor_sync(0xffffffffu, s,  o);
        ss += __shfl_xor_sync(0xffffffffu, ss, o);
    }
    int warp = tid >> 5, lane = tid & 31;
    if (lane == 0) { red0[warp] = s; red1[warp] = ss; }
    __syncthreads();
    if (warp == 0) {
        float a  = (lane < 8) ? red0[lane] : 0.f;
        float a2 = (lane < 8) ? red1[lane] : 0.f;
        #pragma unroll
        for (int o = 4; o > 0; o >>= 1) {
            a  += __shfl_xor_sync(0xffffffffu, a,  o);
            a2 += __shfl_xor_sync(0xffffffffu, a2, o);
        }
        if (lane == 0) { red0[0] = a; red1[0] = a2; }
    }
    __syncthreads();

    float mean = red0[0] * (1.0f / D_MODEL);
    float var  = red1[0] * (1.0f / D_MODEL) - mean * mean;
    float rstd = rsqrtf(var + 1e-5f);

    float4 gv = *(const float4*)(g + tid * 4);
    float4 bv = *(const float4*)(b + tid * 4);
    float o0 = (xv.x - mean) * rstd * gv.x + bv.x;
    float o1 = (xv.y - mean) * rstd * gv.y + bv.y;
    float o2 = (xv.z - mean) * rstd * gv.z + bv.z;
    float o3 = (xv.w - mean) * rstd * gv.w + bv.w;
    uint32_t h01, l01, h23, l23;
    split2h(o0, o1, h01, l01);
    split2h(o2, o3, h23, l23);
    *(uint2*)(oh + (size_t)row * D_MODEL + tid * 4) = make_uint2(h01, h23);
    *(uint2*)(ol + (size_t)row * D_MODEL + tid * 4) = make_uint2(l01, l23);
}

// ---------------- launch ----------------
extern "C" void kernel_launch(void* const* d_in, const int* in_sizes, int n_in,
                              void* d_out, int out_size) {
    const float* x     = (const float*)d_in[0];
    const float* qkv_w = (const float*)d_in[1];
    const float* qkv_b = (const float*)d_in[2];
    const float* out_w = (const float*)d_in[3];
    const float* out_b = (const float*)d_in[4];
    const float* ff1_w = (const float*)d_in[5];
    const float* ff1_b = (const float*)d_in[6];
    const float* ff2_w = (const float*)d_in[7];
    const float* ff2_b = (const float*)d_in[8];
    const float* ln1_g = (const float*)d_in[9];
    const float* ln1_b = (const float*)d_in[10];
    const float* ln2_g = (const float*)d_in[11];
    const float* ln2_b = (const float*)d_in[12];
    float* out = (float*)d_out;

    __half *hh, *hl, *qh, *ql, *ch, *cl, *fh, *fl;
    __half *wq, *wo, *w1, *w2;
    float* x1;
    cudaGetSymbolAddress((void**)&hh, g_hh);  cudaGetSymbolAddress((void**)&hl, g_hl);
    cudaGetSymbolAddress((void**)&qh, g_qh);  cudaGetSymbolAddress((void**)&ql, g_ql);
    cudaGetSymbolAddress((void**)&ch, g_ch);  cudaGetSymbolAddress((void**)&cl, g_cl);
    cudaGetSymbolAddress((void**)&fh, g_fh);  cudaGetSymbolAddress((void**)&fl, g_fl);
    cudaGetSymbolAddress((void**)&x1, g_x1);
    cudaGetSymbolAddress((void**)&wq, g_wq);  cudaGetSymbolAddress((void**)&wo, g_wo);
    cudaGetSymbolAddress((void**)&w1, g_w1);  cudaGetSymbolAddress((void**)&w2, g_w2);

    cudaFuncSetAttribute(hmma_gemm<false, false, true>,
                         cudaFuncAttributeMaxDynamicSharedMemorySize, GEMM_SMEM);
    cudaFuncSetAttribute(hmma_gemm<false, true, false>,
                         cudaFuncAttributeMaxDynamicSharedMemorySize, GEMM_SMEM);
    cudaFuncSetAttribute(hmma_gemm<true, false, true>,
                         cudaFuncAttributeMaxDynamicSharedMemorySize, GEMM_SMEM);
    cudaFuncSetAttribute(attn_hmma,
                         cudaFuncAttributeMaxDynamicSharedMemorySize, ATT_SMEM);

    // 0. weight conversion (transpose + fp16)
    wconv<<<dim3(3 * D_MODEL / 32, D_MODEL / 32), 256>>>(qkv_w, wq, 3 * D_MODEL, D_MODEL);
    wconv<<<dim3(D_MODEL / 32, D_MODEL / 32), 256>>>(out_w, wo, D_MODEL, D_MODEL);
    wconv<<<dim3(FFH / 32, D_MODEL / 32), 256>>>(ff1_w, w1, FFH, D_MODEL);
    wconv<<<dim3(D_MODEL / 32, FFH / 32), 256>>>(ff2_w, w2, D_MODEL, FFH);

    // 1. h = LN1(x) -> hi/lo
    ln_kernel<<<NTOK, 256>>>(x, ln1_g, ln1_b, hh, hl);
    // 2. qkv = h @ qkv_w + qkv_b -> hi/lo
    hmma_gemm<false, false, true><<<dim3(3 * D_MODEL / 128, NTOK / 128), 512, GEMM_SMEM>>>(
        hh, hl, wq, qkv_b, nullptr, nullptr, qh, ql, NTOK, 3 * D_MODEL, D_MODEL);
    // 3. ctx = attention(qkv) -> hi/lo
    attn_hmma<<<dim3(SEQ / 128, NHEAD, BATCH), 256, ATT_SMEM>>>(qh, ql, ch, cl);
    // 4. x1 = ctx @ out_w + out_b + x   (fp32)
    hmma_gemm<false, true, false><<<dim3(D_MODEL / 128, NTOK / 128), 512, GEMM_SMEM>>>(
        ch, cl, wo, out_b, x, x1, nullptr, nullptr, NTOK, D_MODEL, D_MODEL);
    // 5. h2 = LN2(x1) -> hi/lo
    ln_kernel<<<NTOK, 256>>>(x1, ln2_g, ln2_b, hh, hl);
    // 6. ffh = gelu(h2 @ ff1_w + ff1_b) -> hi/lo
    hmma_gemm<true, false, true><<<dim3(FFH / 128, NTOK / 128), 512, GEMM_SMEM>>>(
        hh, hl, w1, ff1_b, nullptr, nullptr, fh, fl, NTOK, FFH, D_MODEL);
    // 7. out = ffh @ ff2_w + ff2_b + x1  (fp32)
    hmma_gemm<false, true, false><<<dim3(D_MODEL / 128, NTOK / 128), 512, GEMM_SMEM>>>(
        fh, fl, w2, ff2_b, x1, out, nullptr, nullptr, NTOK, D_MODEL, FFH);
}